// round 10
// baseline (speedup 1.0000x reference)
#include <cuda_runtime.h>
#include <cuda_fp16.h>
#include <cstdint>
#include <math.h>

// ---------------- problem constants ----------------
#define B_SZ 8192
#define KDIM 1024
#define NDIM 1024
#define ODE_STEPS 6

// ---------------- GEMM config ----------------
#define BM 128
#define BN 128
#define KT 64                            // K elems per chunk (fp16: 128 B/row)
#define NCH (KDIM / KT)                  // 16 chunks
#define STAGES 4
#define TILE_A_BYTES (BM * KT * 2)       // 16 KB
#define TILE_B_BYTES (BN * KT * 2)       // 16 KB
#define STAGE_BYTES (TILE_A_BYTES + 2 * TILE_B_BYTES)   // 48 KB
#define SMEM_TOTAL (STAGES * STAGE_BYTES)               // 192 KB
#define NTHREADS 256
// epilogue prefetch regions in stages 0-2 (free during last chunk), padded strides
#define EPI_EH0 0                         // 128 x 272B  (fp16 tile, conflict-free)
#define EPI_EH1 34816                     // 128 x 272B
#define EPI_HX  69632                     // 128 x 528B  (fp32 tile)

// ---------------- scratch (device globals; no runtime allocation) -----------
static __device__ float  g_h0[(size_t)B_SZ * NDIM];
static __device__ float  g_h1[(size_t)B_SZ * NDIM];
static __device__ __half g_hh0[(size_t)B_SZ * NDIM];
static __device__ __half g_hh1[(size_t)B_SZ * NDIM];
static __device__ __half g_idh[(size_t)B_SZ * NDIM];    // fp16 input_drive
static __device__ __half g_gxh[(size_t)B_SZ * NDIM];    // fp16 gate_x
static __device__ __half g_xh[(size_t)B_SZ * KDIM];
static __device__ __half g_winh[(size_t)NDIM * KDIM];
static __device__ __half g_wrech[(size_t)NDIM * KDIM];
static __device__ __half g_wgxh[(size_t)NDIM * KDIM];
static __device__ __half g_wghh[(size_t)NDIM * KDIM];
static __device__ float  g_scale[NDIM];

// ---------------- helpers ----------------
__device__ __forceinline__ uint32_t swz128(uint32_t off) { return off ^ ((off >> 3) & 0x70); }

__device__ __forceinline__ void cp16(uint32_t s, const void* g) {
    asm volatile("cp.async.cg.shared.global [%0], [%1], 16;" :: "r"(s), "l"(g) : "memory");
}
__device__ __forceinline__ void ldsm4(uint32_t* r, uint32_t addr) {
    asm volatile("ldmatrix.sync.aligned.m8n8.x4.shared.b16 {%0,%1,%2,%3}, [%4];"
                 : "=r"(r[0]), "=r"(r[1]), "=r"(r[2]), "=r"(r[3]) : "r"(addr));
}
__device__ __forceinline__ void mma16816(float* d, const uint32_t* a, const uint32_t* b) {
    asm volatile(
        "mma.sync.aligned.m16n8k16.row.col.f32.f16.f16.f32 "
        "{%0,%1,%2,%3}, {%4,%5,%6,%7}, {%8,%9}, {%0,%1,%2,%3};"
        : "+f"(d[0]), "+f"(d[1]), "+f"(d[2]), "+f"(d[3])
        : "r"(a[0]), "r"(a[1]), "r"(a[2]), "r"(a[3]), "r"(b[0]), "r"(b[1]));
}
__device__ __forceinline__ float fast_tanh(float x) {
    float e = __expf(2.0f * x);
    return 1.0f - 2.0f / (e + 1.0f);
}

// ---------------- single merged prep kernel ----------------
#define L_X  ((B_SZ * KDIM) / 4)
#define L_W  ((NDIM * KDIM) / 4)
#define P_O1 (L_X)
#define P_O2 (P_O1 + L_X)
#define P_O3 (P_O2 + L_W)
#define P_O4 (P_O3 + L_W)
#define P_O5 (P_O4 + L_W)
#define P_TOTAL (P_O5 + NDIM / 4)

__global__ void prep_all(const float* __restrict__ x, const float* __restrict__ h,
                         const float* __restrict__ win, const float* __restrict__ wrec,
                         const float* __restrict__ wg, const float* __restrict__ log_tau,
                         __half* __restrict__ xh, __half* __restrict__ hh,
                         __half* __restrict__ winh, __half* __restrict__ wrech,
                         __half* __restrict__ wgxh, __half* __restrict__ wghh,
                         float* __restrict__ scale) {
    int i = blockIdx.x * blockDim.x + threadIdx.x;
    if (i < P_O1) {
        float4 v = ((const float4*)x)[i];
        ((__half2*)xh)[2 * i]     = __floats2half2_rn(v.x, v.y);
        ((__half2*)xh)[2 * i + 1] = __floats2half2_rn(v.z, v.w);
    } else if (i < P_O2) {
        int j = i - P_O1;
        float4 v = ((const float4*)h)[j];
        ((__half2*)hh)[2 * j]     = __floats2half2_rn(v.x, v.y);
        ((__half2*)hh)[2 * j + 1] = __floats2half2_rn(v.z, v.w);
    } else if (i < P_O3) {
        int j = i - P_O2;
        float4 v = ((const float4*)win)[j];
        ((__half2*)winh)[2 * j]     = __floats2half2_rn(v.x, v.y);
        ((__half2*)winh)[2 * j + 1] = __floats2half2_rn(v.z, v.w);
    } else if (i < P_O4) {
        int j = i - P_O3;
        float4 v = ((const float4*)wrec)[j];
        ((__half2*)wrech)[2 * j]     = __floats2half2_rn(v.x, v.y);
        ((__half2*)wrech)[2 * j + 1] = __floats2half2_rn(v.z, v.w);
    } else if (i < P_O5) {
        int j = i - P_O4;
        int i4 = j * 4;
        int row = i4 >> 10, col = i4 & 1023;
        const float4 vx = *(const float4*)(wg + (size_t)row * 2048 + col);
        const float4 vh = *(const float4*)(wg + (size_t)row * 2048 + 1024 + col);
        ((__half2*)wgxh)[2 * j]     = __floats2half2_rn(vx.x, vx.y);
        ((__half2*)wgxh)[2 * j + 1] = __floats2half2_rn(vx.z, vx.w);
        ((__half2*)wghh)[2 * j]     = __floats2half2_rn(vh.x, vh.y);
        ((__half2*)wghh)[2 * j + 1] = __floats2half2_rn(vh.z, vh.w);
    } else if (i < P_TOTAL) {
        int j = i - P_O5;
        float4 v = ((const float4*)log_tau)[j];
        float4 o;
        o.x = (1.0f / 6.0f) * expf(-v.x);
        o.y = (1.0f / 6.0f) * expf(-v.y);
        o.z = (1.0f / 6.0f) * expf(-v.z);
        o.w = (1.0f / 6.0f) * expf(-v.w);
        ((float4*)scale)[j] = o;
    }
}

// ---------------- dual fp16 tensor-core GEMM with fully fused step ----------
// MODE 0: Oh0 = half(acc0 + b0[n]);  Oh1 = half(acc1 + b1[n])
// MODE 1: drive=tanh(eh0+acc0); gate=sigmoid(eh1+acc1);
//         o = hx + sc[n]*(gate*drive - hx);  Of = o; Oh0 = half(o)
// MODE 2: same as 1 but Of = o and Of2 = o
template <int MODE>
__global__ void __launch_bounds__(NTHREADS, 1)
ltc_fused(const __half* __restrict__ A, const __half* __restrict__ W0,
          const __half* __restrict__ W1,
          const __half* __restrict__ eh0, const __half* __restrict__ eh1,
          const float* __restrict__ b0p, const float* __restrict__ b1p,
          const float* __restrict__ hx, const float* __restrict__ sc,
          float* __restrict__ Of, float* __restrict__ Of2,
          __half* __restrict__ Oh0, __half* __restrict__ Oh1) {
    extern __shared__ char dsm[];
    const uint32_t sbase = (uint32_t)__cvta_generic_to_shared(dsm);
    const int tid = threadIdx.x;
    const int wid = tid >> 5, lid = tid & 31;
    const int wm = wid >> 1, wn = wid & 1;      // 4x2 warp grid; warp tile 32x64
    const int mBase = blockIdx.y * BM;
    const int nBase = blockIdx.x * BN;

    auto load_chunk = [&](int c) {
        const uint32_t st = sbase + (c % STAGES) * STAGE_BYTES;
        const __half* ga  = A  + (size_t)mBase * KDIM + c * KT;
        const __half* gb0 = W0 + (size_t)nBase * KDIM + c * KT;
        const __half* gb1 = W1 + (size_t)nBase * KDIM + c * KT;
        // A, B0, B1: each 128 rows x 8 groups x 16B
#pragma unroll
        for (int i = 0; i < 4; i++) {
            int t = tid + i * NTHREADS;
            int row = t >> 3, cg = t & 7;
            uint32_t sw = swz128((uint32_t)(row * 128 + cg * 16));
            size_t go = (size_t)row * KDIM + cg * 8;
            cp16(st + sw, ga + go);
            cp16(st + TILE_A_BYTES + sw, gb0 + go);
            cp16(st + TILE_A_BYTES + TILE_B_BYTES + sw, gb1 + go);
        }
        asm volatile("cp.async.commit_group;" ::: "memory");
    };

    float acc0[2][8][4], acc1[2][8][4];
#pragma unroll
    for (int mt = 0; mt < 2; mt++)
#pragma unroll
        for (int nt = 0; nt < 8; nt++)
#pragma unroll
            for (int e = 0; e < 4; e++) { acc0[mt][nt][e] = 0.0f; acc1[mt][nt][e] = 0.0f; }

    load_chunk(0);
    load_chunk(1);
    load_chunk(2);

    const int sub = lid >> 3, li = lid & 7;

    for (int kt = 0; kt < NCH; kt++) {
        asm volatile("cp.async.wait_group 2;" ::: "memory");   // chunk kt resident
        __syncthreads();
        if (kt + 3 < NCH) {
            load_chunk(kt + 3);
        } else if (kt == NCH - 1 && MODE != 0) {
            // prefetch epilogue operands into freed stages 0-2 (padded, conflict-free)
#pragma unroll
            for (int i = 0; i < 8; i++) {
                int t = tid + i * NTHREADS;       // 0..2047: 128 rows x 16 groups
                int row = t >> 4, cg = t & 15;
                size_t go = (size_t)(mBase + row) * NDIM + nBase + cg * 8;
                cp16(sbase + EPI_EH0 + row * 272 + cg * 16, eh0 + go);
                cp16(sbase + EPI_EH1 + row * 272 + cg * 16, eh1 + go);
            }
#pragma unroll
            for (int i = 0; i < 16; i++) {
                int t = tid + i * NTHREADS;       // 0..4095: 128 rows x 32 groups
                int row = t >> 5, cg = t & 31;
                cp16(sbase + EPI_HX + row * 528 + cg * 16,
                     hx + (size_t)(mBase + row) * NDIM + nBase + cg * 4);
            }
            asm volatile("cp.async.commit_group;" ::: "memory");
        } else {
            asm volatile("cp.async.commit_group;" ::: "memory");
        }

        const uint32_t tb = sbase + (kt % STAGES) * STAGE_BYTES;
#pragma unroll
        for (int ks = 0; ks < 4; ks++) {
            const int k0 = ks * 16;
            uint32_t af[2][4];
#pragma unroll
            for (int mt = 0; mt < 2; mt++) {
                int row = wm * 32 + mt * 16 + ((sub & 1) << 3) + li;
                int kb = (k0 + ((sub >> 1) << 3)) * 2;
                ldsm4(af[mt], tb + swz128((uint32_t)(row * 128 + kb)));
            }
            {
                uint32_t bf[4][4];
#pragma unroll
                for (int np = 0; np < 4; np++) {
                    int row = wn * 64 + np * 16 + ((sub >> 1) << 3) + li;
                    int kb = (k0 + ((sub & 1) << 3)) * 2;
                    ldsm4(bf[np], tb + TILE_A_BYTES + swz128((uint32_t)(row * 128 + kb)));
                }
#pragma unroll
                for (int mt = 0; mt < 2; mt++)
#pragma unroll
                    for (int nt = 0; nt < 8; nt++)
                        mma16816(acc0[mt][nt], af[mt], &bf[nt >> 1][(nt & 1) * 2]);
            }
            {
                uint32_t bf[4][4];
#pragma unroll
                for (int np = 0; np < 4; np++) {
                    int row = wn * 64 + np * 16 + ((sub >> 1) << 3) + li;
                    int kb = (k0 + ((sub & 1) << 3)) * 2;
                    ldsm4(bf[np], tb + TILE_A_BYTES + TILE_B_BYTES + swz128((uint32_t)(row * 128 + kb)));
                }
#pragma unroll
                for (int mt = 0; mt < 2; mt++)
#pragma unroll
                    for (int nt = 0; nt < 8; nt++)
                        mma16816(acc1[mt][nt], af[mt], &bf[nt >> 1][(nt & 1) * 2]);
            }
        }
    }
    asm volatile("cp.async.wait_group 0;" ::: "memory");
    if (MODE != 0) __syncthreads();   // epilogue tiles loaded by all threads

    // ---------------- fused epilogue ----------------
    const int l4 = lid >> 2, l2 = (lid & 3) * 2;
#pragma unroll
    for (int mt = 0; mt < 2; mt++) {
#pragma unroll
        for (int nt = 0; nt < 8; nt++) {
            const int rl0 = wm * 32 + mt * 16 + l4;   // local row in tile
            const int cl  = wn * 64 + nt * 8 + l2;    // local col in tile
            const int gc = nBase + cl;
            const float* a0 = acc0[mt][nt];
            const float* a1 = acc1[mt][nt];
            float2 scv = make_float2(0.f, 0.f), bb0 = scv, bb1 = scv;
            if (MODE == 0) {
                bb0 = *(const float2*)(b0p + gc);
                bb1 = *(const float2*)(b1p + gc);
            } else {
                scv = *(const float2*)(sc + gc);
            }
#pragma unroll
            for (int hf = 0; hf < 2; hf++) {
                const int rl = rl0 + hf * 8;
                const size_t idx = (size_t)(mBase + rl) * NDIM + gc;
                float v0x = a0[hf * 2], v0y = a0[hf * 2 + 1];
                float v1x = a1[hf * 2], v1y = a1[hf * 2 + 1];
                if (MODE == 0) {
                    *(__half2*)(Oh0 + idx) = __floats2half2_rn(v0x + bb0.x, v0y + bb0.y);
                    *(__half2*)(Oh1 + idx) = __floats2half2_rn(v1x + bb1.x, v1y + bb1.y);
                } else {
                    float2 pe0 = __half22float2(*(const __half2*)(dsm + EPI_EH0 + rl * 272 + cl * 2));
                    float2 pe1 = __half22float2(*(const __half2*)(dsm + EPI_EH1 + rl * 272 + cl * 2));
                    float2 hv  = *(const float2*)(dsm + EPI_HX + rl * 528 + cl * 4);
                    float dx = fast_tanh(pe0.x + v0x);
                    float dy = fast_tanh(pe0.y + v0y);
                    float gx = 1.0f / (1.0f + __expf(-(pe1.x + v1x)));
                    float gy = 1.0f / (1.0f + __expf(-(pe1.y + v1y)));
                    float ox = hv.x + scv.x * (gx * dx - hv.x);
                    float oy = hv.y + scv.y * (gy * dy - hv.y);
                    *(float2*)(Of + idx) = make_float2(ox, oy);
                    if (MODE == 1) {
                        *(__half2*)(Oh0 + idx) = __floats2half2_rn(ox, oy);
                    } else {  // MODE 2
                        *(float2*)(Of2 + idx) = make_float2(ox, oy);
                    }
                }
            }
        }
    }
}

// ---------------- launch ----------------
extern "C" void kernel_launch(void* const* d_in, const int* in_sizes, int n_in,
                              void* d_out, int out_size) {
    const float* x        = (const float*)d_in[0];
    const float* h_in     = (const float*)d_in[1];
    const float* log_tau  = (const float*)d_in[2];
    const float* W_in_w   = (const float*)d_in[3];
    const float* W_in_b   = (const float*)d_in[4];
    const float* W_rec_w  = (const float*)d_in[5];
    const float* W_gate_w = (const float*)d_in[6];
    const float* W_gate_b = (const float*)d_in[7];
    (void)in_sizes; (void)n_in;

    float *ph0, *ph1, *psc;
    __half *phh0, *phh1, *pidh, *pgxh, *pxh, *pwinh, *pwrech, *pwgxh, *pwghh;
    cudaGetSymbolAddress((void**)&ph0, g_h0);
    cudaGetSymbolAddress((void**)&ph1, g_h1);
    cudaGetSymbolAddress((void**)&phh0, g_hh0);
    cudaGetSymbolAddress((void**)&phh1, g_hh1);
    cudaGetSymbolAddress((void**)&pidh, g_idh);
    cudaGetSymbolAddress((void**)&pgxh, g_gxh);
    cudaGetSymbolAddress((void**)&pxh, g_xh);
    cudaGetSymbolAddress((void**)&pwinh, g_winh);
    cudaGetSymbolAddress((void**)&pwrech, g_wrech);
    cudaGetSymbolAddress((void**)&pwgxh, g_wgxh);
    cudaGetSymbolAddress((void**)&pwghh, g_wghh);
    cudaGetSymbolAddress((void**)&psc, g_scale);

    cudaFuncSetAttribute(ltc_fused<0>, cudaFuncAttributeMaxDynamicSharedMemorySize, SMEM_TOTAL);
    cudaFuncSetAttribute(ltc_fused<1>, cudaFuncAttributeMaxDynamicSharedMemorySize, SMEM_TOTAL);
    cudaFuncSetAttribute(ltc_fused<2>, cudaFuncAttributeMaxDynamicSharedMemorySize, SMEM_TOTAL);

    const size_t n = (size_t)B_SZ * NDIM;

    prep_all<<<(P_TOTAL + 255) / 256, 256>>>(
        x, h_in, W_in_w, W_rec_w, W_gate_w, log_tau,
        pxh, phh0, pwinh, pwrech, pwgxh, pwghh, psc);

    dim3 grid(NDIM / BN, B_SZ / BM);  // (8, 64) = 512 CTAs

    ltc_fused<0><<<grid, NTHREADS, SMEM_TOTAL>>>(
        pxh, pwinh, pwgxh, nullptr, nullptr, W_in_b, W_gate_b,
        nullptr, nullptr, nullptr, nullptr, pidh, pgxh);

    float* out = (float*)d_out;
    int dup = ((size_t)out_size >= 2 * n) ? 1 : 0;
    float* out2 = dup ? (out + n) : out;

    const float*  hf_cur = h_in;
    const __half* hh_cur = phh0;
    for (int s = 0; s < ODE_STEPS; s++) {
        float*  tgt_f = (s & 1) ? ph1 : ph0;
        __half* tgt_h = (s & 1) ? phh0 : phh1;
        if (s < ODE_STEPS - 1) {
            ltc_fused<1><<<grid, NTHREADS, SMEM_TOTAL>>>(
                hh_cur, pwrech, pwghh, pidh, pgxh, nullptr, nullptr,
                hf_cur, psc, tgt_f, nullptr, tgt_h, nullptr);
            hf_cur = tgt_f;
            hh_cur = tgt_h;
        } else {
            ltc_fused<2><<<grid, NTHREADS, SMEM_TOTAL>>>(
                hh_cur, pwrech, pwghh, pidh, pgxh, nullptr, nullptr,
                hf_cur, psc, out, out2, nullptr, nullptr);
        }
    }
}

// round 12
// speedup vs baseline: 1.2325x; 1.2325x over previous
#include <cuda_runtime.h>
#include <cuda_fp16.h>
#include <cstdint>
#include <math.h>

// ---------------- problem constants ----------------
#define B_SZ 8192
#define KDIM 1024
#define NDIM 1024
#define ODE_STEPS 6

// ---------------- GEMM config ----------------
#define BM 128
#define BN 64
#define KT 64                            // K elems per chunk (fp16: 128 B/row)
#define NCH (KDIM / KT)                  // 16 chunks
#define STAGES 3
#define TILE_A_BYTES (BM * KT * 2)       // 16 KB
#define TILE_B_BYTES (BN * KT * 2)       // 8 KB
#define STAGE_BYTES (TILE_A_BYTES + 2 * TILE_B_BYTES)   // 32 KB
#define SMEM_TOTAL (STAGES * STAGE_BYTES)               // 96 KB
#define NTHREADS 128                     // 4 warps, 2x2 grid of 64x32 warp tiles
// epilogue prefetch regions in stages 1+2 ONLY (stage 0 is consumed at kt=15!)
#define EPI_EH0 (STAGE_BYTES)             // 32 KB: 128 x 128B (fp16 tile)
#define EPI_EH1 (STAGE_BYTES + 16384)     // 48 KB: 128 x 128B
#define EPI_HX  (2 * STAGE_BYTES)         // 64 KB: 128 x 256B (fp32 tile) -> ends at 96 KB

// ---------------- scratch (device globals; no runtime allocation) -----------
static __device__ float  g_h0[(size_t)B_SZ * NDIM];
static __device__ float  g_h1[(size_t)B_SZ * NDIM];
static __device__ __half g_hh0[(size_t)B_SZ * NDIM];
static __device__ __half g_hh1[(size_t)B_SZ * NDIM];
static __device__ __half g_idh[(size_t)B_SZ * NDIM];    // fp16 input_drive
static __device__ __half g_gxh[(size_t)B_SZ * NDIM];    // fp16 gate_x
static __device__ __half g_xh[(size_t)B_SZ * KDIM];
static __device__ __half g_winh[(size_t)NDIM * KDIM];
static __device__ __half g_wrech[(size_t)NDIM * KDIM];
static __device__ __half g_wgxh[(size_t)NDIM * KDIM];
static __device__ __half g_wghh[(size_t)NDIM * KDIM];
static __device__ float  g_scale[NDIM];

// ---------------- helpers ----------------
__device__ __forceinline__ uint32_t swz128(uint32_t off) { return off ^ ((off >> 3) & 0x70); }

__device__ __forceinline__ void cp16(uint32_t s, const void* g) {
    asm volatile("cp.async.cg.shared.global [%0], [%1], 16;" :: "r"(s), "l"(g) : "memory");
}
__device__ __forceinline__ void ldsm4(uint32_t* r, uint32_t addr) {
    asm volatile("ldmatrix.sync.aligned.m8n8.x4.shared.b16 {%0,%1,%2,%3}, [%4];"
                 : "=r"(r[0]), "=r"(r[1]), "=r"(r[2]), "=r"(r[3]) : "r"(addr));
}
__device__ __forceinline__ void mma16816(float* d, const uint32_t* a, const uint32_t* b) {
    asm volatile(
        "mma.sync.aligned.m16n8k16.row.col.f32.f16.f16.f32 "
        "{%0,%1,%2,%3}, {%4,%5,%6,%7}, {%8,%9}, {%0,%1,%2,%3};"
        : "+f"(d[0]), "+f"(d[1]), "+f"(d[2]), "+f"(d[3])
        : "r"(a[0]), "r"(a[1]), "r"(a[2]), "r"(a[3]), "r"(b[0]), "r"(b[1]));
}
__device__ __forceinline__ float fast_tanh(float x) {
    float e = __expf(2.0f * x);
    return 1.0f - 2.0f / (e + 1.0f);
}

// ---------------- single merged prep kernel ----------------
#define L_X  ((B_SZ * KDIM) / 4)
#define L_W  ((NDIM * KDIM) / 4)
#define P_O1 (L_X)
#define P_O2 (P_O1 + L_X)
#define P_O3 (P_O2 + L_W)
#define P_O4 (P_O3 + L_W)
#define P_O5 (P_O4 + L_W)
#define P_TOTAL (P_O5 + NDIM / 4)

__global__ void prep_all(const float* __restrict__ x, const float* __restrict__ h,
                         const float* __restrict__ win, const float* __restrict__ wrec,
                         const float* __restrict__ wg, const float* __restrict__ log_tau,
                         __half* __restrict__ xh, __half* __restrict__ hh,
                         __half* __restrict__ winh, __half* __restrict__ wrech,
                         __half* __restrict__ wgxh, __half* __restrict__ wghh,
                         float* __restrict__ scale) {
    int i = blockIdx.x * blockDim.x + threadIdx.x;
    if (i < P_O1) {
        float4 v = ((const float4*)x)[i];
        ((__half2*)xh)[2 * i]     = __floats2half2_rn(v.x, v.y);
        ((__half2*)xh)[2 * i + 1] = __floats2half2_rn(v.z, v.w);
    } else if (i < P_O2) {
        int j = i - P_O1;
        float4 v = ((const float4*)h)[j];
        ((__half2*)hh)[2 * j]     = __floats2half2_rn(v.x, v.y);
        ((__half2*)hh)[2 * j + 1] = __floats2half2_rn(v.z, v.w);
    } else if (i < P_O3) {
        int j = i - P_O2;
        float4 v = ((const float4*)win)[j];
        ((__half2*)winh)[2 * j]     = __floats2half2_rn(v.x, v.y);
        ((__half2*)winh)[2 * j + 1] = __floats2half2_rn(v.z, v.w);
    } else if (i < P_O4) {
        int j = i - P_O3;
        float4 v = ((const float4*)wrec)[j];
        ((__half2*)wrech)[2 * j]     = __floats2half2_rn(v.x, v.y);
        ((__half2*)wrech)[2 * j + 1] = __floats2half2_rn(v.z, v.w);
    } else if (i < P_O5) {
        int j = i - P_O4;
        int i4 = j * 4;
        int row = i4 >> 10, col = i4 & 1023;
        const float4 vx = *(const float4*)(wg + (size_t)row * 2048 + col);
        const float4 vh = *(const float4*)(wg + (size_t)row * 2048 + 1024 + col);
        ((__half2*)wgxh)[2 * j]     = __floats2half2_rn(vx.x, vx.y);
        ((__half2*)wgxh)[2 * j + 1] = __floats2half2_rn(vx.z, vx.w);
        ((__half2*)wghh)[2 * j]     = __floats2half2_rn(vh.x, vh.y);
        ((__half2*)wghh)[2 * j + 1] = __floats2half2_rn(vh.z, vh.w);
    } else if (i < P_TOTAL) {
        int j = i - P_O5;
        float4 v = ((const float4*)log_tau)[j];
        float4 o;
        o.x = (1.0f / 6.0f) * expf(-v.x);
        o.y = (1.0f / 6.0f) * expf(-v.y);
        o.z = (1.0f / 6.0f) * expf(-v.z);
        o.w = (1.0f / 6.0f) * expf(-v.w);
        ((float4*)scale)[j] = o;
    }
}

// ---------------- dual fp16 tensor-core GEMM with fully fused step ----------
// MODE 0: Oh0 = half(acc0 + b0[n]);  Oh1 = half(acc1 + b1[n])
// MODE 1: drive=tanh(eh0+acc0); gate=sigmoid(eh1+acc1);
//         o = hx + sc[n]*(gate*drive - hx);  Of = o; Oh0 = half(o)
// MODE 2: same as 1 but Of = o and Of2 = o
template <int MODE>
__global__ void __launch_bounds__(NTHREADS, 2)
ltc_fused(const __half* __restrict__ A, const __half* __restrict__ W0,
          const __half* __restrict__ W1,
          const __half* __restrict__ eh0, const __half* __restrict__ eh1,
          const float* __restrict__ b0p, const float* __restrict__ b1p,
          const float* __restrict__ hx, const float* __restrict__ sc,
          float* __restrict__ Of, float* __restrict__ Of2,
          __half* __restrict__ Oh0, __half* __restrict__ Oh1) {
    extern __shared__ char dsm[];
    const uint32_t sbase = (uint32_t)__cvta_generic_to_shared(dsm);
    const int tid = threadIdx.x;
    const int wid = tid >> 5, lid = tid & 31;
    const int wm = wid >> 1, wn = wid & 1;      // 2x2 warp grid; warp tile 64x32
    const int mBase = blockIdx.y * BM;
    const int nBase = blockIdx.x * BN;

    auto load_chunk = [&](int c) {
        const uint32_t st = sbase + (c % STAGES) * STAGE_BYTES;
        const __half* ga  = A  + (size_t)mBase * KDIM + c * KT;
        const __half* gb0 = W0 + (size_t)nBase * KDIM + c * KT;
        const __half* gb1 = W1 + (size_t)nBase * KDIM + c * KT;
        // A: 128 rows x 8 groups = 1024 cp16
#pragma unroll
        for (int i = 0; i < 8; i++) {
            int t = tid + i * NTHREADS;
            int row = t >> 3, cg = t & 7;
            uint32_t sw = swz128((uint32_t)(row * 128 + cg * 16));
            cp16(st + sw, ga + (size_t)row * KDIM + cg * 8);
        }
        // B0/B1: 64 rows x 8 groups = 512 cp16 each
#pragma unroll
        for (int i = 0; i < 4; i++) {
            int t = tid + i * NTHREADS;
            int row = t >> 3, cg = t & 7;
            uint32_t sw = swz128((uint32_t)(row * 128 + cg * 16));
            size_t go = (size_t)row * KDIM + cg * 8;
            cp16(st + TILE_A_BYTES + sw, gb0 + go);
            cp16(st + TILE_A_BYTES + TILE_B_BYTES + sw, gb1 + go);
        }
        asm volatile("cp.async.commit_group;" ::: "memory");
    };

    float acc0[4][4][4], acc1[4][4][4];
#pragma unroll
    for (int mt = 0; mt < 4; mt++)
#pragma unroll
        for (int nt = 0; nt < 4; nt++)
#pragma unroll
            for (int e = 0; e < 4; e++) { acc0[mt][nt][e] = 0.0f; acc1[mt][nt][e] = 0.0f; }

    load_chunk(0);
    load_chunk(1);

    const int sub = lid >> 3, li = lid & 7;

    for (int kt = 0; kt < NCH; kt++) {
        asm volatile("cp.async.wait_group 1;" ::: "memory");
        __syncthreads();
        if (kt + 2 < NCH) {
            load_chunk(kt + 2);
        } else if (kt == NCH - 1 && MODE != 0) {
            // prefetch epilogue operands into stages 1+2 (drained; stage 0 in use)
#pragma unroll
            for (int i = 0; i < 8; i++) {
                int t = tid + i * NTHREADS;        // 0..1023: 128 rows x 8 groups
                int row = t >> 3, cg = t & 7;
                size_t go = (size_t)(mBase + row) * NDIM + nBase + cg * 8;
                cp16(sbase + EPI_EH0 + row * 128 + cg * 16, eh0 + go);
                cp16(sbase + EPI_EH1 + row * 128 + cg * 16, eh1 + go);
            }
#pragma unroll
            for (int i = 0; i < 16; i++) {
                int t = tid + i * NTHREADS;        // 0..2047: 128 rows x 16 groups
                int row = t >> 4, cg = t & 15;
                cp16(sbase + EPI_HX + row * 256 + cg * 16,
                     hx + (size_t)(mBase + row) * NDIM + nBase + cg * 4);
            }
            asm volatile("cp.async.commit_group;" ::: "memory");
        } else {
            asm volatile("cp.async.commit_group;" ::: "memory");
        }

        const uint32_t tb = sbase + (kt % STAGES) * STAGE_BYTES;
#pragma unroll
        for (int ks = 0; ks < 4; ks++) {
            const int k0 = ks * 16;
            uint32_t af[4][4];
#pragma unroll
            for (int mt = 0; mt < 4; mt++) {
                int row = wm * 64 + mt * 16 + ((sub & 1) << 3) + li;
                int kb = (k0 + ((sub >> 1) << 3)) * 2;
                ldsm4(af[mt], tb + swz128((uint32_t)(row * 128 + kb)));
            }
            {
                uint32_t bf[2][4];
#pragma unroll
                for (int np = 0; np < 2; np++) {
                    int row = wn * 32 + np * 16 + ((sub >> 1) << 3) + li;
                    int kb = (k0 + ((sub & 1) << 3)) * 2;
                    ldsm4(bf[np], tb + TILE_A_BYTES + swz128((uint32_t)(row * 128 + kb)));
                }
#pragma unroll
                for (int mt = 0; mt < 4; mt++)
#pragma unroll
                    for (int nt = 0; nt < 4; nt++)
                        mma16816(acc0[mt][nt], af[mt], &bf[nt >> 1][(nt & 1) * 2]);
            }
            {
                uint32_t bf[2][4];
#pragma unroll
                for (int np = 0; np < 2; np++) {
                    int row = wn * 32 + np * 16 + ((sub >> 1) << 3) + li;
                    int kb = (k0 + ((sub & 1) << 3)) * 2;
                    ldsm4(bf[np], tb + TILE_A_BYTES + TILE_B_BYTES + swz128((uint32_t)(row * 128 + kb)));
                }
#pragma unroll
                for (int mt = 0; mt < 4; mt++)
#pragma unroll
                    for (int nt = 0; nt < 4; nt++)
                        mma16816(acc1[mt][nt], af[mt], &bf[nt >> 1][(nt & 1) * 2]);
            }
        }
    }
    asm volatile("cp.async.wait_group 0;" ::: "memory");
    if (MODE != 0) __syncthreads();   // epilogue tiles loaded by all threads

    // ---------------- fused epilogue ----------------
    const int l4 = lid >> 2, l2 = (lid & 3) * 2;
#pragma unroll
    for (int mt = 0; mt < 4; mt++) {
#pragma unroll
        for (int nt = 0; nt < 4; nt++) {
            const int rl0 = wm * 64 + mt * 16 + l4;   // local row in tile
            const int cl  = wn * 32 + nt * 8 + l2;    // local col in tile
            const int gc = nBase + cl;
            const float* a0 = acc0[mt][nt];
            const float* a1 = acc1[mt][nt];
            float2 scv = make_float2(0.f, 0.f), bb0 = scv, bb1 = scv;
            if (MODE == 0) {
                bb0 = *(const float2*)(b0p + gc);
                bb1 = *(const float2*)(b1p + gc);
            } else {
                scv = *(const float2*)(sc + gc);
            }
#pragma unroll
            for (int hf = 0; hf < 2; hf++) {
                const int rl = rl0 + hf * 8;
                const size_t idx = (size_t)(mBase + rl) * NDIM + gc;
                float v0x = a0[hf * 2], v0y = a0[hf * 2 + 1];
                float v1x = a1[hf * 2], v1y = a1[hf * 2 + 1];
                if (MODE == 0) {
                    *(__half2*)(Oh0 + idx) = __floats2half2_rn(v0x + bb0.x, v0y + bb0.y);
                    *(__half2*)(Oh1 + idx) = __floats2half2_rn(v1x + bb1.x, v1y + bb1.y);
                } else {
                    float2 pe0 = __half22float2(*(const __half2*)(dsm + EPI_EH0 + rl * 128 + cl * 2));
                    float2 pe1 = __half22float2(*(const __half2*)(dsm + EPI_EH1 + rl * 128 + cl * 2));
                    float2 hv  = *(const float2*)(dsm + EPI_HX + rl * 256 + cl * 4);
                    float dx = fast_tanh(pe0.x + v0x);
                    float dy = fast_tanh(pe0.y + v0y);
                    float gx = 1.0f / (1.0f + __expf(-(pe1.x + v1x)));
                    float gy = 1.0f / (1.0f + __expf(-(pe1.y + v1y)));
                    float ox = hv.x + scv.x * (gx * dx - hv.x);
                    float oy = hv.y + scv.y * (gy * dy - hv.y);
                    *(float2*)(Of + idx) = make_float2(ox, oy);
                    if (MODE == 1) {
                        *(__half2*)(Oh0 + idx) = __floats2half2_rn(ox, oy);
                    } else {  // MODE 2
                        *(float2*)(Of2 + idx) = make_float2(ox, oy);
                    }
                }
            }
        }
    }
}

// ---------------- launch ----------------
extern "C" void kernel_launch(void* const* d_in, const int* in_sizes, int n_in,
                              void* d_out, int out_size) {
    const float* x        = (const float*)d_in[0];
    const float* h_in     = (const float*)d_in[1];
    const float* log_tau  = (const float*)d_in[2];
    const float* W_in_w   = (const float*)d_in[3];
    const float* W_in_b   = (const float*)d_in[4];
    const float* W_rec_w  = (const float*)d_in[5];
    const float* W_gate_w = (const float*)d_in[6];
    const float* W_gate_b = (const float*)d_in[7];
    (void)in_sizes; (void)n_in;

    float *ph0, *ph1, *psc;
    __half *phh0, *phh1, *pidh, *pgxh, *pxh, *pwinh, *pwrech, *pwgxh, *pwghh;
    cudaGetSymbolAddress((void**)&ph0, g_h0);
    cudaGetSymbolAddress((void**)&ph1, g_h1);
    cudaGetSymbolAddress((void**)&phh0, g_hh0);
    cudaGetSymbolAddress((void**)&phh1, g_hh1);
    cudaGetSymbolAddress((void**)&pidh, g_idh);
    cudaGetSymbolAddress((void**)&pgxh, g_gxh);
    cudaGetSymbolAddress((void**)&pxh, g_xh);
    cudaGetSymbolAddress((void**)&pwinh, g_winh);
    cudaGetSymbolAddress((void**)&pwrech, g_wrech);
    cudaGetSymbolAddress((void**)&pwgxh, g_wgxh);
    cudaGetSymbolAddress((void**)&pwghh, g_wghh);
    cudaGetSymbolAddress((void**)&psc, g_scale);

    cudaFuncSetAttribute(ltc_fused<0>, cudaFuncAttributeMaxDynamicSharedMemorySize, SMEM_TOTAL);
    cudaFuncSetAttribute(ltc_fused<1>, cudaFuncAttributeMaxDynamicSharedMemorySize, SMEM_TOTAL);
    cudaFuncSetAttribute(ltc_fused<2>, cudaFuncAttributeMaxDynamicSharedMemorySize, SMEM_TOTAL);

    const size_t n = (size_t)B_SZ * NDIM;

    prep_all<<<(P_TOTAL + 255) / 256, 256>>>(
        x, h_in, W_in_w, W_rec_w, W_gate_w, log_tau,
        pxh, phh0, pwinh, pwrech, pwgxh, pwghh, psc);

    dim3 grid(NDIM / BN, B_SZ / BM);  // (16, 64) = 1024 CTAs

    ltc_fused<0><<<grid, NTHREADS, SMEM_TOTAL>>>(
        pxh, pwinh, pwgxh, nullptr, nullptr, W_in_b, W_gate_b,
        nullptr, nullptr, nullptr, nullptr, pidh, pgxh);

    float* out = (float*)d_out;
    int dup = ((size_t)out_size >= 2 * n) ? 1 : 0;
    float* out2 = dup ? (out + n) : out;

    const float*  hf_cur = h_in;
    const __half* hh_cur = phh0;
    for (int s = 0; s < ODE_STEPS; s++) {
        float*  tgt_f = (s & 1) ? ph1 : ph0;
        __half* tgt_h = (s & 1) ? phh0 : phh1;
        if (s < ODE_STEPS - 1) {
            ltc_fused<1><<<grid, NTHREADS, SMEM_TOTAL>>>(
                hh_cur, pwrech, pwghh, pidh, pgxh, nullptr, nullptr,
                hf_cur, psc, tgt_f, nullptr, tgt_h, nullptr);
            hf_cur = tgt_f;
            hh_cur = tgt_h;
        } else {
            ltc_fused<2><<<grid, NTHREADS, SMEM_TOTAL>>>(
                hh_cur, pwrech, pwghh, pidh, pgxh, nullptr, nullptr,
                hf_cur, psc, out, out2, nullptr, nullptr);
        }
    }
}

// round 13
// speedup vs baseline: 1.3288x; 1.0781x over previous
#include <cuda_runtime.h>
#include <cuda_fp16.h>
#include <cstdint>
#include <math.h>

// ---------------- problem constants ----------------
#define B_SZ 8192
#define KDIM 1024
#define NDIM 1024
#define ODE_STEPS 6

// ---------------- GEMM config ----------------
#define BM 128
#define BN 64
#define KT 64                            // K elems per chunk (fp16: 128 B/row)
#define NCH (KDIM / KT)                  // 16 chunks
#define STAGES 3
#define TILE_A_BYTES (BM * KT * 2)       // 16 KB
#define TILE_B_BYTES (BN * KT * 2)       // 8 KB
#define STAGE_BYTES (TILE_A_BYTES + 2 * TILE_B_BYTES)   // 32 KB
#define MB_OFF (STAGES * STAGE_BYTES)                   // 98304: mbarriers
#define SMEM_TOTAL (MB_OFF + 64)                        // 98368 B
#define NTHREADS 256
// epilogue prefetch regions (stages 1+2; both drained when used at kt=15)
#define EPI_EH0 (STAGE_BYTES)                 // 32 KB (128x64 fp16)
#define EPI_EH1 (STAGE_BYTES + 16384)         // 48 KB
#define EPI_HX  (2 * STAGE_BYTES)             // 64 KB (128x64 fp32)

// ---------------- scratch (device globals; no runtime allocation) -----------
static __device__ float  g_h0[(size_t)B_SZ * NDIM];
static __device__ float  g_h1[(size_t)B_SZ * NDIM];
static __device__ __half g_hh0[(size_t)B_SZ * NDIM];
static __device__ __half g_hh1[(size_t)B_SZ * NDIM];
static __device__ __half g_idh[(size_t)B_SZ * NDIM];    // fp16 input_drive
static __device__ __half g_gxh[(size_t)B_SZ * NDIM];    // fp16 gate_x
static __device__ __half g_xh[(size_t)B_SZ * KDIM];
static __device__ __half g_winh[(size_t)NDIM * KDIM];
static __device__ __half g_wrech[(size_t)NDIM * KDIM];
static __device__ __half g_wgxh[(size_t)NDIM * KDIM];
static __device__ __half g_wghh[(size_t)NDIM * KDIM];
static __device__ float  g_scale[NDIM];

// ---------------- helpers ----------------
__device__ __forceinline__ uint32_t swz128(uint32_t off) { return off ^ ((off >> 3) & 0x70); }

__device__ __forceinline__ void cp16(uint32_t s, const void* g) {
    asm volatile("cp.async.cg.shared.global [%0], [%1], 16;" :: "r"(s), "l"(g) : "memory");
}
__device__ __forceinline__ void ldsm4(uint32_t* r, uint32_t addr) {
    asm volatile("ldmatrix.sync.aligned.m8n8.x4.shared.b16 {%0,%1,%2,%3}, [%4];"
                 : "=r"(r[0]), "=r"(r[1]), "=r"(r[2]), "=r"(r[3]) : "r"(addr));
}
__device__ __forceinline__ void mma16816(float* d, const uint32_t* a, const uint32_t* b) {
    asm volatile(
        "mma.sync.aligned.m16n8k16.row.col.f32.f16.f16.f32 "
        "{%0,%1,%2,%3}, {%4,%5,%6,%7}, {%8,%9}, {%0,%1,%2,%3};"
        : "+f"(d[0]), "+f"(d[1]), "+f"(d[2]), "+f"(d[3])
        : "r"(a[0]), "r"(a[1]), "r"(a[2]), "r"(a[3]), "r"(b[0]), "r"(b[1]));
}
__device__ __forceinline__ float fast_tanh(float x) {
    float e = __expf(2.0f * x);
    return 1.0f - 2.0f / (e + 1.0f);
}
__device__ __forceinline__ void mbar_init(uint32_t a, uint32_t cnt) {
    asm volatile("mbarrier.init.shared.b64 [%0], %1;" :: "r"(a), "r"(cnt) : "memory");
}
__device__ __forceinline__ void mbar_wait(uint32_t a, uint32_t ph) {
    asm volatile(
        "{\n\t.reg .pred P;\n"
        "W%=:\n\t"
        "mbarrier.try_wait.parity.acquire.cta.shared::cta.b64 P, [%0], %1, 0x989680;\n\t"
        "@P bra D%=;\n\t"
        "bra W%=;\n"
        "D%=:\n\t}"
        :: "r"(a), "r"(ph) : "memory");
}
__device__ __forceinline__ void mbar_arrive(uint32_t a) {
    asm volatile("mbarrier.arrive.shared.b64 _, [%0];" :: "r"(a) : "memory");
}
__device__ __forceinline__ void cpasync_arrive(uint32_t a) {
    asm volatile("cp.async.mbarrier.arrive.noinc.shared.b64 [%0];" :: "r"(a) : "memory");
}

// ---------------- single merged prep kernel ----------------
#define L_X  ((B_SZ * KDIM) / 4)
#define L_W  ((NDIM * KDIM) / 4)
#define P_O1 (L_X)
#define P_O2 (P_O1 + L_X)
#define P_O3 (P_O2 + L_W)
#define P_O4 (P_O3 + L_W)
#define P_O5 (P_O4 + L_W)
#define P_TOTAL (P_O5 + NDIM / 4)

__global__ void prep_all(const float* __restrict__ x, const float* __restrict__ h,
                         const float* __restrict__ win, const float* __restrict__ wrec,
                         const float* __restrict__ wg, const float* __restrict__ log_tau,
                         __half* __restrict__ xh, __half* __restrict__ hh,
                         __half* __restrict__ winh, __half* __restrict__ wrech,
                         __half* __restrict__ wgxh, __half* __restrict__ wghh,
                         float* __restrict__ scale) {
    int i = blockIdx.x * blockDim.x + threadIdx.x;
    if (i < P_O1) {
        float4 v = ((const float4*)x)[i];
        ((__half2*)xh)[2 * i]     = __floats2half2_rn(v.x, v.y);
        ((__half2*)xh)[2 * i + 1] = __floats2half2_rn(v.z, v.w);
    } else if (i < P_O2) {
        int j = i - P_O1;
        float4 v = ((const float4*)h)[j];
        ((__half2*)hh)[2 * j]     = __floats2half2_rn(v.x, v.y);
        ((__half2*)hh)[2 * j + 1] = __floats2half2_rn(v.z, v.w);
    } else if (i < P_O3) {
        int j = i - P_O2;
        float4 v = ((const float4*)win)[j];
        ((__half2*)winh)[2 * j]     = __floats2half2_rn(v.x, v.y);
        ((__half2*)winh)[2 * j + 1] = __floats2half2_rn(v.z, v.w);
    } else if (i < P_O4) {
        int j = i - P_O3;
        float4 v = ((const float4*)wrec)[j];
        ((__half2*)wrech)[2 * j]     = __floats2half2_rn(v.x, v.y);
        ((__half2*)wrech)[2 * j + 1] = __floats2half2_rn(v.z, v.w);
    } else if (i < P_O5) {
        int j = i - P_O4;
        int i4 = j * 4;
        int row = i4 >> 10, col = i4 & 1023;
        const float4 vx = *(const float4*)(wg + (size_t)row * 2048 + col);
        const float4 vh = *(const float4*)(wg + (size_t)row * 2048 + 1024 + col);
        ((__half2*)wgxh)[2 * j]     = __floats2half2_rn(vx.x, vx.y);
        ((__half2*)wgxh)[2 * j + 1] = __floats2half2_rn(vx.z, vx.w);
        ((__half2*)wghh)[2 * j]     = __floats2half2_rn(vh.x, vh.y);
        ((__half2*)wghh)[2 * j + 1] = __floats2half2_rn(vh.z, vh.w);
    } else if (i < P_TOTAL) {
        int j = i - P_O5;
        float4 v = ((const float4*)log_tau)[j];
        float4 o;
        o.x = (1.0f / 6.0f) * expf(-v.x);
        o.y = (1.0f / 6.0f) * expf(-v.y);
        o.z = (1.0f / 6.0f) * expf(-v.z);
        o.w = (1.0f / 6.0f) * expf(-v.w);
        ((float4*)scale)[j] = o;
    }
}

// ---------------- dual fp16 tensor-core GEMM, mbarrier pipeline -------------
// MODE 0: Oh0 = half(acc0 + b0[n]);  Oh1 = half(acc1 + b1[n])
// MODE 1: drive=tanh(eh0+acc0); gate=sigmoid(eh1+acc1);
//         o = hx + sc[n]*(gate*drive - hx);  Of = o; Oh0 = half(o)
// MODE 2: same as 1 but Of = o and Of2 = o
template <int MODE>
__global__ void __launch_bounds__(NTHREADS, 2)
ltc_fused(const __half* __restrict__ A, const __half* __restrict__ W0,
          const __half* __restrict__ W1,
          const __half* __restrict__ eh0, const __half* __restrict__ eh1,
          const float* __restrict__ b0p, const float* __restrict__ b1p,
          const float* __restrict__ hx, const float* __restrict__ sc,
          float* __restrict__ Of, float* __restrict__ Of2,
          __half* __restrict__ Oh0, __half* __restrict__ Oh1) {
    extern __shared__ char dsm[];
    const uint32_t sbase = (uint32_t)__cvta_generic_to_shared(dsm);
    const int tid = threadIdx.x;
    const int wid = tid >> 5, lid = tid & 31;
    const int wm = wid >> 1, wn = wid & 1;      // 4x2 warp grid; warp tile 32x32
    const int mBase = blockIdx.y * BM;
    const int nBase = blockIdx.x * BN;

    const uint32_t mbF = sbase + MB_OFF;        // full[s]  at +0,8,16
    const uint32_t mbE = sbase + MB_OFF + 24;   // empty[s] at +24,32,40

    if (tid == 0) {
#pragma unroll
        for (int s = 0; s < 3; s++) {
            mbar_init(mbF + 8 * s, NTHREADS);   // 256 cp.async arrivals
            mbar_init(mbE + 8 * s, 8);          // 8 warp arrivals
        }
    }
    __syncthreads();

    auto load_chunk = [&](int c) {              // no commit_group in mainloop
        const uint32_t st = sbase + (c % STAGES) * STAGE_BYTES;
        const __half* ga  = A  + (size_t)mBase * KDIM + c * KT;
        const __half* gb0 = W0 + (size_t)nBase * KDIM + c * KT;
        const __half* gb1 = W1 + (size_t)nBase * KDIM + c * KT;
#pragma unroll
        for (int i = 0; i < 4; i++) {
            int t = tid + i * NTHREADS;
            int row = t >> 3, cg = t & 7;
            uint32_t sw = swz128((uint32_t)(row * 128 + cg * 16));
            cp16(st + sw, ga + (size_t)row * KDIM + cg * 8);
        }
#pragma unroll
        for (int i = 0; i < 2; i++) {
            int t = tid + i * NTHREADS;
            int row = t >> 3, cg = t & 7;
            uint32_t sw = swz128((uint32_t)(row * 128 + cg * 16));
            size_t go = (size_t)row * KDIM + cg * 8;
            cp16(st + TILE_A_BYTES + sw, gb0 + go);
            cp16(st + TILE_A_BYTES + TILE_B_BYTES + sw, gb1 + go);
        }
    };

    float acc0[2][4][4], acc1[2][4][4];
#pragma unroll
    for (int mt = 0; mt < 2; mt++)
#pragma unroll
        for (int nt = 0; nt < 4; nt++)
#pragma unroll
            for (int e = 0; e < 4; e++) { acc0[mt][nt][e] = 0.0f; acc1[mt][nt][e] = 0.0f; }

    // prologue: stages 0,1 (no empty-wait needed for first STAGES loads)
    load_chunk(0); cpasync_arrive(mbF + 0);
    load_chunk(1); cpasync_arrive(mbF + 8);

    const int sub = lid >> 3, li = lid & 7;
    uint32_t fp = 0, ep = 0;   // per-stage parity bitmasks (bits 0..2)

    for (int kt = 0; kt < NCH; kt++) {
        // ---- producer slot: chunk kt+2 (or epilogue prefetch at kt==15) ----
        const int L = kt + 2;
        if (L < NCH) {
            const int ls = L % 3;
            if (L >= STAGES) {   // readers of chunk L-3 must be done
                mbar_wait(mbE + 8 * ls, (ep >> ls) & 1);
                ep ^= 1u << ls;
            }
            load_chunk(L);
            cpasync_arrive(mbF + 8 * ls);
        } else if (kt == NCH - 1 && MODE != 0) {
            // stages 1+2 reused: wait readers of chunks 13 (stage1) and 14 (stage2)
            mbar_wait(mbE + 8 * 1, (ep >> 1) & 1);
            mbar_wait(mbE + 8 * 2, (ep >> 2) & 1);
#pragma unroll
            for (int i = 0; i < 4; i++) {
                int t = tid + i * NTHREADS;        // 0..1023: 128 rows x 8 x 16B
                int row = t >> 3, cg = t & 7;
                size_t go = (size_t)(mBase + row) * NDIM + nBase + cg * 8;
                cp16(sbase + EPI_EH0 + row * 128 + cg * 16, eh0 + go);
                cp16(sbase + EPI_EH1 + row * 128 + cg * 16, eh1 + go);
            }
#pragma unroll
            for (int i = 0; i < 8; i++) {
                int t = tid + i * NTHREADS;        // 0..2047: 128 rows x 16 x 16B
                int row = t >> 4, cg = t & 15;
                cp16(sbase + EPI_HX + row * 256 + cg * 16,
                     hx + (size_t)(mBase + row) * NDIM + nBase + cg * 4);
            }
            asm volatile("cp.async.commit_group;" ::: "memory");
        }

        // ---- consumer: chunk kt ----
        const int cs = kt % 3;
        mbar_wait(mbF + 8 * cs, (fp >> cs) & 1);
        fp ^= 1u << cs;

        const uint32_t tb = sbase + cs * STAGE_BYTES;
#pragma unroll
        for (int ks = 0; ks < 4; ks++) {
            const int k0 = ks * 16;
            uint32_t af[2][4];
#pragma unroll
            for (int mt = 0; mt < 2; mt++) {
                int row = wm * 32 + mt * 16 + ((sub & 1) << 3) + li;
                int kb = (k0 + ((sub >> 1) << 3)) * 2;
                ldsm4(af[mt], tb + swz128((uint32_t)(row * 128 + kb)));
            }
            {
                uint32_t bf[2][4];
#pragma unroll
                for (int np = 0; np < 2; np++) {
                    int row = wn * 32 + np * 16 + ((sub >> 1) << 3) + li;
                    int kb = (k0 + ((sub & 1) << 3)) * 2;
                    ldsm4(bf[np], tb + TILE_A_BYTES + swz128((uint32_t)(row * 128 + kb)));
                }
#pragma unroll
                for (int mt = 0; mt < 2; mt++)
#pragma unroll
                    for (int nt = 0; nt < 4; nt++)
                        mma16816(acc0[mt][nt], af[mt], &bf[nt >> 1][(nt & 1) * 2]);
            }
            {
                uint32_t bf[2][4];
#pragma unroll
                for (int np = 0; np < 2; np++) {
                    int row = wn * 32 + np * 16 + ((sub >> 1) << 3) + li;
                    int kb = (k0 + ((sub & 1) << 3)) * 2;
                    ldsm4(bf[np], tb + TILE_A_BYTES + TILE_B_BYTES + swz128((uint32_t)(row * 128 + kb)));
                }
#pragma unroll
                for (int mt = 0; mt < 2; mt++)
#pragma unroll
                    for (int nt = 0; nt < 4; nt++)
                        mma16816(acc1[mt][nt], af[mt], &bf[nt >> 1][(nt & 1) * 2]);
            }
        }
        __syncwarp();
        if (lid == 0) mbar_arrive(mbE + 8 * cs);   // release stage cs
    }

    if (MODE != 0) {
        asm volatile("cp.async.wait_group 0;" ::: "memory");  // epi prefetch done (own)
        __syncthreads();                                      // visible to all
    }

    // ---------------- fused epilogue ----------------
    const int l4 = lid >> 2, l2 = (lid & 3) * 2;
#pragma unroll
    for (int mt = 0; mt < 2; mt++) {
#pragma unroll
        for (int nt = 0; nt < 4; nt++) {
            const int rl0 = wm * 32 + mt * 16 + l4;   // local row in tile
            const int cl  = wn * 32 + nt * 8 + l2;    // local col in tile
            const int gc = nBase + cl;
            const float* a0 = acc0[mt][nt];
            const float* a1 = acc1[mt][nt];
            float2 scv = make_float2(0.f, 0.f), bb0 = scv, bb1 = scv;
            if (MODE == 0) {
                bb0 = *(const float2*)(b0p + gc);
                bb1 = *(const float2*)(b1p + gc);
            } else {
                scv = *(const float2*)(sc + gc);
            }
#pragma unroll
            for (int hf = 0; hf < 2; hf++) {
                const int rl = rl0 + hf * 8;
                const size_t idx = (size_t)(mBase + rl) * NDIM + gc;
                float v0x = a0[hf * 2], v0y = a0[hf * 2 + 1];
                float v1x = a1[hf * 2], v1y = a1[hf * 2 + 1];
                if (MODE == 0) {
                    *(__half2*)(Oh0 + idx) = __floats2half2_rn(v0x + bb0.x, v0y + bb0.y);
                    *(__half2*)(Oh1 + idx) = __floats2half2_rn(v1x + bb1.x, v1y + bb1.y);
                } else {
                    float2 pe0 = __half22float2(*(const __half2*)(dsm + EPI_EH0 + rl * 128 + cl * 2));
                    float2 pe1 = __half22float2(*(const __half2*)(dsm + EPI_EH1 + rl * 128 + cl * 2));
                    float2 hv  = *(const float2*)(dsm + EPI_HX + rl * 256 + cl * 4);
                    float dx = fast_tanh(pe0.x + v0x);
                    float dy = fast_tanh(pe0.y + v0y);
                    float gx = 1.0f / (1.0f + __expf(-(pe1.x + v1x)));
                    float gy = 1.0f / (1.0f + __expf(-(pe1.y + v1y)));
                    float ox = hv.x + scv.x * (gx * dx - hv.x);
                    float oy = hv.y + scv.y * (gy * dy - hv.y);
                    *(float2*)(Of + idx) = make_float2(ox, oy);
                    if (MODE == 1) {
                        *(__half2*)(Oh0 + idx) = __floats2half2_rn(ox, oy);
                    } else {  // MODE 2
                        *(float2*)(Of2 + idx) = make_float2(ox, oy);
                    }
                }
            }
        }
    }
}

// ---------------- launch ----------------
extern "C" void kernel_launch(void* const* d_in, const int* in_sizes, int n_in,
                              void* d_out, int out_size) {
    const float* x        = (const float*)d_in[0];
    const float* h_in     = (const float*)d_in[1];
    const float* log_tau  = (const float*)d_in[2];
    const float* W_in_w   = (const float*)d_in[3];
    const float* W_in_b   = (const float*)d_in[4];
    const float* W_rec_w  = (const float*)d_in[5];
    const float* W_gate_w = (const float*)d_in[6];
    const float* W_gate_b = (const float*)d_in[7];
    (void)in_sizes; (void)n_in;

    float *ph0, *ph1, *psc;
    __half *phh0, *phh1, *pidh, *pgxh, *pxh, *pwinh, *pwrech, *pwgxh, *pwghh;
    cudaGetSymbolAddress((void**)&ph0, g_h0);
    cudaGetSymbolAddress((void**)&ph1, g_h1);
    cudaGetSymbolAddress((void**)&phh0, g_hh0);
    cudaGetSymbolAddress((void**)&phh1, g_hh1);
    cudaGetSymbolAddress((void**)&pidh, g_idh);
    cudaGetSymbolAddress((void**)&pgxh, g_gxh);
    cudaGetSymbolAddress((void**)&pxh, g_xh);
    cudaGetSymbolAddress((void**)&pwinh, g_winh);
    cudaGetSymbolAddress((void**)&pwrech, g_wrech);
    cudaGetSymbolAddress((void**)&pwgxh, g_wgxh);
    cudaGetSymbolAddress((void**)&pwghh, g_wghh);
    cudaGetSymbolAddress((void**)&psc, g_scale);

    cudaFuncSetAttribute(ltc_fused<0>, cudaFuncAttributeMaxDynamicSharedMemorySize, SMEM_TOTAL);
    cudaFuncSetAttribute(ltc_fused<1>, cudaFuncAttributeMaxDynamicSharedMemorySize, SMEM_TOTAL);
    cudaFuncSetAttribute(ltc_fused<2>, cudaFuncAttributeMaxDynamicSharedMemorySize, SMEM_TOTAL);

    const size_t n = (size_t)B_SZ * NDIM;

    prep_all<<<(P_TOTAL + 255) / 256, 256>>>(
        x, h_in, W_in_w, W_rec_w, W_gate_w, log_tau,
        pxh, phh0, pwinh, pwrech, pwgxh, pwghh, psc);

    dim3 grid(NDIM / BN, B_SZ / BM);  // (16, 64) = 1024 CTAs

    ltc_fused<0><<<grid, NTHREADS, SMEM_TOTAL>>>(
        pxh, pwinh, pwgxh, nullptr, nullptr, W_in_b, W_gate_b,
        nullptr, nullptr, nullptr, nullptr, pidh, pgxh);

    float* out = (float*)d_out;
    int dup = ((size_t)out_size >= 2 * n) ? 1 : 0;
    float* out2 = dup ? (out + n) : out;

    const float*  hf_cur = h_in;
    const __half* hh_cur = phh0;
    for (int s = 0; s < ODE_STEPS; s++) {
        float*  tgt_f = (s & 1) ? ph1 : ph0;
        __half* tgt_h = (s & 1) ? phh0 : phh1;
        if (s < ODE_STEPS - 1) {
            ltc_fused<1><<<grid, NTHREADS, SMEM_TOTAL>>>(
                hh_cur, pwrech, pwghh, pidh, pgxh, nullptr, nullptr,
                hf_cur, psc, tgt_f, nullptr, tgt_h, nullptr);
            hf_cur = tgt_f;
            hh_cur = tgt_h;
        } else {
            ltc_fused<2><<<grid, NTHREADS, SMEM_TOTAL>>>(
                hh_cur, pwrech, pwghh, pidh, pgxh, nullptr, nullptr,
                hf_cur, psc, out, out2, nullptr, nullptr);
        }
    }
}

// round 15
// speedup vs baseline: 1.3518x; 1.0173x over previous
#include <cuda_runtime.h>
#include <cuda_fp16.h>
#include <cstdint>
#include <math.h>

// ---------------- problem constants ----------------
#define B_SZ 8192
#define KDIM 1024
#define NDIM 1024
#define ODE_STEPS 6

// ---------------- GEMM config ----------------
#define BM 128
#define BN 64
#define KT 64                            // K elems per chunk (fp16: 128 B/row)
#define NCH (KDIM / KT)                  // 16 chunks
#define STAGES 3
#define TILE_A_BYTES (BM * KT * 2)       // 16 KB
#define TILE_B_BYTES (BN * KT * 2)       // 8 KB
#define STAGE_BYTES (TILE_A_BYTES + 2 * TILE_B_BYTES)   // 32 KB
#define SMEM_TOTAL (STAGES * STAGE_BYTES)               // 96 KB
#define NTHREADS 256
// epilogue prefetch regions (stages 1+2; both drained when used at kt=15)
#define EPI_EH0 (STAGE_BYTES)                 // 32 KB (128x64 fp16)
#define EPI_EH1 (STAGE_BYTES + 16384)         // 48 KB
#define EPI_HX  (2 * STAGE_BYTES)             // 64 KB (128x64 fp32)

// ---------------- scratch (device globals; no runtime allocation) -----------
static __device__ float  g_h0[(size_t)B_SZ * NDIM];
static __device__ float  g_h1[(size_t)B_SZ * NDIM];
static __device__ __half g_hh0[(size_t)B_SZ * NDIM];
static __device__ __half g_hh1[(size_t)B_SZ * NDIM];
static __device__ __half g_idh[(size_t)B_SZ * NDIM];    // fp16 input_drive
static __device__ __half g_gxh[(size_t)B_SZ * NDIM];    // fp16 gate_x
static __device__ __half g_xh[(size_t)B_SZ * KDIM];
static __device__ __half g_winh[(size_t)NDIM * KDIM];
static __device__ __half g_wrech[(size_t)NDIM * KDIM];
static __device__ __half g_wgxh[(size_t)NDIM * KDIM];
static __device__ __half g_wghh[(size_t)NDIM * KDIM];
static __device__ float  g_scale[NDIM];

// ---------------- helpers ----------------
__device__ __forceinline__ uint32_t swz128(uint32_t off) { return off ^ ((off >> 3) & 0x70); }

__device__ __forceinline__ void cp16(uint32_t s, const void* g) {
    asm volatile("cp.async.cg.shared.global [%0], [%1], 16;" :: "r"(s), "l"(g) : "memory");
}
__device__ __forceinline__ void ldsm4(uint32_t* r, uint32_t addr) {
    asm volatile("ldmatrix.sync.aligned.m8n8.x4.shared.b16 {%0,%1,%2,%3}, [%4];"
                 : "=r"(r[0]), "=r"(r[1]), "=r"(r[2]), "=r"(r[3]) : "r"(addr));
}
__device__ __forceinline__ void mma16816(float* d, const uint32_t* a, const uint32_t* b) {
    asm volatile(
        "mma.sync.aligned.m16n8k16.row.col.f32.f16.f16.f32 "
        "{%0,%1,%2,%3}, {%4,%5,%6,%7}, {%8,%9}, {%0,%1,%2,%3};"
        : "+f"(d[0]), "+f"(d[1]), "+f"(d[2]), "+f"(d[3])
        : "r"(a[0]), "r"(a[1]), "r"(a[2]), "r"(a[3]), "r"(b[0]), "r"(b[1]));
}
__device__ __forceinline__ float fast_tanh(float x) {
    float e = __expf(2.0f * x);
    return 1.0f - 2.0f / (e + 1.0f);
}

// ---------------- single merged prep kernel ----------------
#define L_X  ((B_SZ * KDIM) / 4)
#define L_W  ((NDIM * KDIM) / 4)
#define P_O1 (L_X)
#define P_O2 (P_O1 + L_X)
#define P_O3 (P_O2 + L_W)
#define P_O4 (P_O3 + L_W)
#define P_O5 (P_O4 + L_W)
#define P_TOTAL (P_O5 + NDIM / 4)

__global__ void prep_all(const float* __restrict__ x, const float* __restrict__ h,
                         const float* __restrict__ win, const float* __restrict__ wrec,
                         const float* __restrict__ wg, const float* __restrict__ log_tau,
                         __half* __restrict__ xh, __half* __restrict__ hh,
                         __half* __restrict__ winh, __half* __restrict__ wrech,
                         __half* __restrict__ wgxh, __half* __restrict__ wghh,
                         float* __restrict__ scale) {
    int i = blockIdx.x * blockDim.x + threadIdx.x;
    if (i < P_O1) {
        float4 v = ((const float4*)x)[i];
        ((__half2*)xh)[2 * i]     = __floats2half2_rn(v.x, v.y);
        ((__half2*)xh)[2 * i + 1] = __floats2half2_rn(v.z, v.w);
    } else if (i < P_O2) {
        int j = i - P_O1;
        float4 v = ((const float4*)h)[j];
        ((__half2*)hh)[2 * j]     = __floats2half2_rn(v.x, v.y);
        ((__half2*)hh)[2 * j + 1] = __floats2half2_rn(v.z, v.w);
    } else if (i < P_O3) {
        int j = i - P_O2;
        float4 v = ((const float4*)win)[j];
        ((__half2*)winh)[2 * j]     = __floats2half2_rn(v.x, v.y);
        ((__half2*)winh)[2 * j + 1] = __floats2half2_rn(v.z, v.w);
    } else if (i < P_O4) {
        int j = i - P_O3;
        float4 v = ((const float4*)wrec)[j];
        ((__half2*)wrech)[2 * j]     = __floats2half2_rn(v.x, v.y);
        ((__half2*)wrech)[2 * j + 1] = __floats2half2_rn(v.z, v.w);
    } else if (i < P_O5) {
        int j = i - P_O4;
        int i4 = j * 4;
        int row = i4 >> 10, col = i4 & 1023;
        const float4 vx = *(const float4*)(wg + (size_t)row * 2048 + col);
        const float4 vh = *(const float4*)(wg + (size_t)row * 2048 + 1024 + col);
        ((__half2*)wgxh)[2 * j]     = __floats2half2_rn(vx.x, vx.y);
        ((__half2*)wgxh)[2 * j + 1] = __floats2half2_rn(vx.z, vx.w);
        ((__half2*)wghh)[2 * j]     = __floats2half2_rn(vh.x, vh.y);
        ((__half2*)wghh)[2 * j + 1] = __floats2half2_rn(vh.z, vh.w);
    } else if (i < P_TOTAL) {
        int j = i - P_O5;
        float4 v = ((const float4*)log_tau)[j];
        float4 o;
        o.x = (1.0f / 6.0f) * expf(-v.x);
        o.y = (1.0f / 6.0f) * expf(-v.y);
        o.z = (1.0f / 6.0f) * expf(-v.z);
        o.w = (1.0f / 6.0f) * expf(-v.w);
        ((float4*)scale)[j] = o;
    }
}

// ---------------- dual fp16 tensor-core GEMM with fully fused step ----------
// MODE 0: Oh0 = half(acc0 + b0[n]);  Oh1 = half(acc1 + b1[n])
// MODE 1: drive=tanh(eh0+acc0); gate=sigmoid(eh1+acc1);
//         o = hx + sc[n]*(gate*drive - hx);  Of = o; Oh0 = half(o)
// MODE 2: same as 1 but Of = o and Of2 = o
template <int MODE>
__global__ void __launch_bounds__(NTHREADS, 2)
ltc_fused(const __half* __restrict__ A, const __half* __restrict__ W0,
          const __half* __restrict__ W1,
          const __half* __restrict__ eh0, const __half* __restrict__ eh1,
          const float* __restrict__ b0p, const float* __restrict__ b1p,
          const float* __restrict__ hx, const float* __restrict__ sc,
          float* __restrict__ Of, float* __restrict__ Of2,
          __half* __restrict__ Oh0, __half* __restrict__ Oh1) {
    extern __shared__ char dsm[];
    const uint32_t sbase = (uint32_t)__cvta_generic_to_shared(dsm);
    const int tid = threadIdx.x;
    const int wid = tid >> 5, lid = tid & 31;
    const int wm = wid >> 1, wn = wid & 1;      // 4x2 warp grid; warp tile 32x32
    const int mBase = blockIdx.y * BM;
    const int nBase = blockIdx.x * BN;

    auto load_chunk = [&](int c) {
        const uint32_t st = sbase + (c % STAGES) * STAGE_BYTES;
        const __half* ga  = A  + (size_t)mBase * KDIM + c * KT;
        const __half* gb0 = W0 + (size_t)nBase * KDIM + c * KT;
        const __half* gb1 = W1 + (size_t)nBase * KDIM + c * KT;
#pragma unroll
        for (int i = 0; i < 4; i++) {
            int t = tid + i * NTHREADS;
            int row = t >> 3, cg = t & 7;
            uint32_t sw = swz128((uint32_t)(row * 128 + cg * 16));
            cp16(st + sw, ga + (size_t)row * KDIM + cg * 8);
        }
#pragma unroll
        for (int i = 0; i < 2; i++) {
            int t = tid + i * NTHREADS;
            int row = t >> 3, cg = t & 7;
            uint32_t sw = swz128((uint32_t)(row * 128 + cg * 16));
            size_t go = (size_t)row * KDIM + cg * 8;
            cp16(st + TILE_A_BYTES + sw, gb0 + go);
            cp16(st + TILE_A_BYTES + TILE_B_BYTES + sw, gb1 + go);
        }
        asm volatile("cp.async.commit_group;" ::: "memory");
    };

    float acc0[2][4][4], acc1[2][4][4];
#pragma unroll
    for (int mt = 0; mt < 2; mt++)
#pragma unroll
        for (int nt = 0; nt < 4; nt++)
#pragma unroll
            for (int e = 0; e < 4; e++) { acc0[mt][nt][e] = 0.0f; acc1[mt][nt][e] = 0.0f; }

    load_chunk(0);
    load_chunk(1);

    const int sub = lid >> 3, li = lid & 7;

    for (int kt = 0; kt < NCH; kt++) {
        asm volatile("cp.async.wait_group 1;" ::: "memory");
        __syncthreads();
        if (kt + 2 < NCH) {
            load_chunk(kt + 2);
        } else if (kt == NCH - 1 && MODE != 0) {
            // last chunk: prefetch epilogue operands into stages 1+2 (drained)
#pragma unroll
            for (int i = 0; i < 4; i++) {
                int t = tid + i * NTHREADS;        // 0..1023: 128 rows x 8 x 16B
                int row = t >> 3, cg = t & 7;
                size_t go = (size_t)(mBase + row) * NDIM + nBase + cg * 8;
                cp16(sbase + EPI_EH0 + row * 128 + cg * 16, eh0 + go);
                cp16(sbase + EPI_EH1 + row * 128 + cg * 16, eh1 + go);
            }
#pragma unroll
            for (int i = 0; i < 8; i++) {
                int t = tid + i * NTHREADS;        // 0..2047: 128 rows x 16 x 16B
                int row = t >> 4, cg = t & 15;
                cp16(sbase + EPI_HX + row * 256 + cg * 16,
                     hx + (size_t)(mBase + row) * NDIM + nBase + cg * 4);
            }
            asm volatile("cp.async.commit_group;" ::: "memory");
        } else {
            asm volatile("cp.async.commit_group;" ::: "memory");
        }

        const uint32_t tb = sbase + (kt % STAGES) * STAGE_BYTES;
#pragma unroll
        for (int ks = 0; ks < 4; ks++) {
            const int k0 = ks * 16;
            // load ALL fragments first (af + bf0 + bf1), full swizzle math as round 9
            uint32_t af[2][4], bf0[2][4], bf1[2][4];
#pragma unroll
            for (int mt = 0; mt < 2; mt++) {
                int row = wm * 32 + mt * 16 + ((sub & 1) << 3) + li;
                int kb = (k0 + ((sub >> 1) << 3)) * 2;
                ldsm4(af[mt], tb + swz128((uint32_t)(row * 128 + kb)));
            }
#pragma unroll
            for (int np = 0; np < 2; np++) {
                int row = wn * 32 + np * 16 + ((sub >> 1) << 3) + li;
                int kb = (k0 + ((sub & 1) << 3)) * 2;
                ldsm4(bf0[np], tb + TILE_A_BYTES + swz128((uint32_t)(row * 128 + kb)));
            }
#pragma unroll
            for (int np = 0; np < 2; np++) {
                int row = wn * 32 + np * 16 + ((sub >> 1) << 3) + li;
                int kb = (k0 + ((sub & 1) << 3)) * 2;
                ldsm4(bf1[np], tb + TILE_A_BYTES + TILE_B_BYTES + swz128((uint32_t)(row * 128 + kb)));
            }
            // then run all 16 MMAs back-to-back
#pragma unroll
            for (int mt = 0; mt < 2; mt++)
#pragma unroll
                for (int nt = 0; nt < 4; nt++)
                    mma16816(acc0[mt][nt], af[mt], &bf0[nt >> 1][(nt & 1) * 2]);
#pragma unroll
            for (int mt = 0; mt < 2; mt++)
#pragma unroll
                for (int nt = 0; nt < 4; nt++)
                    mma16816(acc1[mt][nt], af[mt], &bf1[nt >> 1][(nt & 1) * 2]);
        }
    }
    asm volatile("cp.async.wait_group 0;" ::: "memory");
    if (MODE != 0) __syncthreads();   // epilogue tiles loaded by all threads

    // ---------------- fused epilogue ----------------
    const int l4 = lid >> 2, l2 = (lid & 3) * 2;
#pragma unroll
    for (int mt = 0; mt < 2; mt++) {
#pragma unroll
        for (int nt = 0; nt < 4; nt++) {
            const int rl0 = wm * 32 + mt * 16 + l4;   // local row in tile
            const int cl  = wn * 32 + nt * 8 + l2;    // local col in tile
            const int gc = nBase + cl;
            const float* a0 = acc0[mt][nt];
            const float* a1 = acc1[mt][nt];
            float2 scv = make_float2(0.f, 0.f), bb0 = scv, bb1 = scv;
            if (MODE == 0) {
                bb0 = *(const float2*)(b0p + gc);
                bb1 = *(const float2*)(b1p + gc);
            } else {
                scv = *(const float2*)(sc + gc);
            }
#pragma unroll
            for (int hf = 0; hf < 2; hf++) {
                const int rl = rl0 + hf * 8;
                const size_t idx = (size_t)(mBase + rl) * NDIM + gc;
                float v0x = a0[hf * 2], v0y = a0[hf * 2 + 1];
                float v1x = a1[hf * 2], v1y = a1[hf * 2 + 1];
                if (MODE == 0) {
                    *(__half2*)(Oh0 + idx) = __floats2half2_rn(v0x + bb0.x, v0y + bb0.y);
                    *(__half2*)(Oh1 + idx) = __floats2half2_rn(v1x + bb1.x, v1y + bb1.y);
                } else {
                    float2 pe0 = __half22float2(*(const __half2*)(dsm + EPI_EH0 + rl * 128 + cl * 2));
                    float2 pe1 = __half22float2(*(const __half2*)(dsm + EPI_EH1 + rl * 128 + cl * 2));
                    float2 hv  = *(const float2*)(dsm + EPI_HX + rl * 256 + cl * 4);
                    float dx = fast_tanh(pe0.x + v0x);
                    float dy = fast_tanh(pe0.y + v0y);
                    float gx = 1.0f / (1.0f + __expf(-(pe1.x + v1x)));
                    float gy = 1.0f / (1.0f + __expf(-(pe1.y + v1y)));
                    float ox = hv.x + scv.x * (gx * dx - hv.x);
                    float oy = hv.y + scv.y * (gy * dy - hv.y);
                    *(float2*)(Of + idx) = make_float2(ox, oy);
                    if (MODE == 1) {
                        *(__half2*)(Oh0 + idx) = __floats2half2_rn(ox, oy);
                    } else {  // MODE 2
                        *(float2*)(Of2 + idx) = make_float2(ox, oy);
                    }
                }
            }
        }
    }
}

// ---------------- launch ----------------
extern "C" void kernel_launch(void* const* d_in, const int* in_sizes, int n_in,
                              void* d_out, int out_size) {
    const float* x        = (const float*)d_in[0];
    const float* h_in     = (const float*)d_in[1];
    const float* log_tau  = (const float*)d_in[2];
    const float* W_in_w   = (const float*)d_in[3];
    const float* W_in_b   = (const float*)d_in[4];
    const float* W_rec_w  = (const float*)d_in[5];
    const float* W_gate_w = (const float*)d_in[6];
    const float* W_gate_b = (const float*)d_in[7];
    (void)in_sizes; (void)n_in;

    float *ph0, *ph1, *psc;
    __half *phh0, *phh1, *pidh, *pgxh, *pxh, *pwinh, *pwrech, *pwgxh, *pwghh;
    cudaGetSymbolAddress((void**)&ph0, g_h0);
    cudaGetSymbolAddress((void**)&ph1, g_h1);
    cudaGetSymbolAddress((void**)&phh0, g_hh0);
    cudaGetSymbolAddress((void**)&phh1, g_hh1);
    cudaGetSymbolAddress((void**)&pidh, g_idh);
    cudaGetSymbolAddress((void**)&pgxh, g_gxh);
    cudaGetSymbolAddress((void**)&pxh, g_xh);
    cudaGetSymbolAddress((void**)&pwinh, g_winh);
    cudaGetSymbolAddress((void**)&pwrech, g_wrech);
    cudaGetSymbolAddress((void**)&pwgxh, g_wgxh);
    cudaGetSymbolAddress((void**)&pwghh, g_wghh);
    cudaGetSymbolAddress((void**)&psc, g_scale);

    cudaFuncSetAttribute(ltc_fused<0>, cudaFuncAttributeMaxDynamicSharedMemorySize, SMEM_TOTAL);
    cudaFuncSetAttribute(ltc_fused<1>, cudaFuncAttributeMaxDynamicSharedMemorySize, SMEM_TOTAL);
    cudaFuncSetAttribute(ltc_fused<2>, cudaFuncAttributeMaxDynamicSharedMemorySize, SMEM_TOTAL);

    const size_t n = (size_t)B_SZ * NDIM;

    prep_all<<<(P_TOTAL + 255) / 256, 256>>>(
        x, h_in, W_in_w, W_rec_w, W_gate_w, log_tau,
        pxh, phh0, pwinh, pwrech, pwgxh, pwghh, psc);

    dim3 grid(NDIM / BN, B_SZ / BM);  // (16, 64) = 1024 CTAs

    ltc_fused<0><<<grid, NTHREADS, SMEM_TOTAL>>>(
        pxh, pwinh, pwgxh, nullptr, nullptr, W_in_b, W_gate_b,
        nullptr, nullptr, nullptr, nullptr, pidh, pgxh);

    float* out = (float*)d_out;
    int dup = ((size_t)out_size >= 2 * n) ? 1 : 0;
    float* out2 = dup ? (out + n) : out;

    const float*  hf_cur = h_in;
    const __half* hh_cur = phh0;
    for (int s = 0; s < ODE_STEPS; s++) {
        float*  tgt_f = (s & 1) ? ph1 : ph0;
        __half* tgt_h = (s & 1) ? phh0 : phh1;
        if (s < ODE_STEPS - 1) {
            ltc_fused<1><<<grid, NTHREADS, SMEM_TOTAL>>>(
                hh_cur, pwrech, pwghh, pidh, pgxh, nullptr, nullptr,
                hf_cur, psc, tgt_f, nullptr, tgt_h, nullptr);
            hf_cur = tgt_f;
            hh_cur = tgt_h;
        } else {
            ltc_fused<2><<<grid, NTHREADS, SMEM_TOTAL>>>(
                hh_cur, pwrech, pwghh, pidh, pgxh, nullptr, nullptr,
                hf_cur, psc, out, out2, nullptr, nullptr);
        }
    }
}

// round 16
// speedup vs baseline: 1.3794x; 1.0204x over previous
#include <cuda_runtime.h>
#include <cuda_fp16.h>
#include <cstdint>
#include <math.h>

// ---------------- problem constants ----------------
#define B_SZ 8192
#define KDIM 1024
#define NDIM 1024
#define ODE_STEPS 6

// ---------------- GEMM config ----------------
#define BM 128
#define BN 64
#define KT 64                            // K elems per chunk (fp16: 128 B/row)
#define NCH (KDIM / KT)                  // 16 chunks
#define STAGES 3
#define TILE_A_BYTES (BM * KT * 2)       // 16 KB
#define TILE_B_BYTES (BN * KT * 2)       // 8 KB
#define STAGE_BYTES (TILE_A_BYTES + 2 * TILE_B_BYTES)   // 32 KB
#define SMEM_TOTAL (STAGES * STAGE_BYTES)               // 96 KB
#define NTHREADS 256
// epilogue prefetch regions (stages 1+2; both drained when used at kt=15)
// all fp16 now: three 16 KB tiles (128 x 128B)
#define EPI_EH0 (STAGE_BYTES)                 // 32 KB
#define EPI_EH1 (STAGE_BYTES + 16384)         // 48 KB
#define EPI_HXH (2 * STAGE_BYTES)             // 64 KB

// ---------------- scratch (device globals; no runtime allocation) -----------
static __device__ __half g_hh0[(size_t)B_SZ * NDIM];    // fp16 h ping (state)
static __device__ __half g_hh1[(size_t)B_SZ * NDIM];    // fp16 h pong (state)
static __device__ __half g_idh[(size_t)B_SZ * NDIM];    // fp16 input_drive
static __device__ __half g_gxh[(size_t)B_SZ * NDIM];    // fp16 gate_x
static __device__ __half g_xh[(size_t)B_SZ * KDIM];
static __device__ __half g_winh[(size_t)NDIM * KDIM];
static __device__ __half g_wrech[(size_t)NDIM * KDIM];
static __device__ __half g_wgxh[(size_t)NDIM * KDIM];
static __device__ __half g_wghh[(size_t)NDIM * KDIM];
static __device__ float  g_scale[NDIM];

// ---------------- helpers ----------------
__device__ __forceinline__ uint32_t swz128(uint32_t off) { return off ^ ((off >> 3) & 0x70); }

__device__ __forceinline__ void cp16(uint32_t s, const void* g) {
    asm volatile("cp.async.cg.shared.global [%0], [%1], 16;" :: "r"(s), "l"(g) : "memory");
}
__device__ __forceinline__ void ldsm4(uint32_t* r, uint32_t addr) {
    asm volatile("ldmatrix.sync.aligned.m8n8.x4.shared.b16 {%0,%1,%2,%3}, [%4];"
                 : "=r"(r[0]), "=r"(r[1]), "=r"(r[2]), "=r"(r[3]) : "r"(addr));
}
__device__ __forceinline__ void mma16816(float* d, const uint32_t* a, const uint32_t* b) {
    asm volatile(
        "mma.sync.aligned.m16n8k16.row.col.f32.f16.f16.f32 "
        "{%0,%1,%2,%3}, {%4,%5,%6,%7}, {%8,%9}, {%0,%1,%2,%3};"
        : "+f"(d[0]), "+f"(d[1]), "+f"(d[2]), "+f"(d[3])
        : "r"(a[0]), "r"(a[1]), "r"(a[2]), "r"(a[3]), "r"(b[0]), "r"(b[1]));
}
__device__ __forceinline__ float fast_tanh(float x) {
    float e = __expf(2.0f * x);
    return 1.0f - 2.0f / (e + 1.0f);
}

// ---------------- single merged prep kernel ----------------
#define L_X  ((B_SZ * KDIM) / 4)
#define L_W  ((NDIM * KDIM) / 4)
#define P_O1 (L_X)
#define P_O2 (P_O1 + L_X)
#define P_O3 (P_O2 + L_W)
#define P_O4 (P_O3 + L_W)
#define P_O5 (P_O4 + L_W)
#define P_TOTAL (P_O5 + NDIM / 4)

__global__ void prep_all(const float* __restrict__ x, const float* __restrict__ h,
                         const float* __restrict__ win, const float* __restrict__ wrec,
                         const float* __restrict__ wg, const float* __restrict__ log_tau,
                         __half* __restrict__ xh, __half* __restrict__ hh,
                         __half* __restrict__ winh, __half* __restrict__ wrech,
                         __half* __restrict__ wgxh, __half* __restrict__ wghh,
                         float* __restrict__ scale) {
    int i = blockIdx.x * blockDim.x + threadIdx.x;
    if (i < P_O1) {
        float4 v = ((const float4*)x)[i];
        ((__half2*)xh)[2 * i]     = __floats2half2_rn(v.x, v.y);
        ((__half2*)xh)[2 * i + 1] = __floats2half2_rn(v.z, v.w);
    } else if (i < P_O2) {
        int j = i - P_O1;
        float4 v = ((const float4*)h)[j];
        ((__half2*)hh)[2 * j]     = __floats2half2_rn(v.x, v.y);
        ((__half2*)hh)[2 * j + 1] = __floats2half2_rn(v.z, v.w);
    } else if (i < P_O3) {
        int j = i - P_O2;
        float4 v = ((const float4*)win)[j];
        ((__half2*)winh)[2 * j]     = __floats2half2_rn(v.x, v.y);
        ((__half2*)winh)[2 * j + 1] = __floats2half2_rn(v.z, v.w);
    } else if (i < P_O4) {
        int j = i - P_O3;
        float4 v = ((const float4*)wrec)[j];
        ((__half2*)wrech)[2 * j]     = __floats2half2_rn(v.x, v.y);
        ((__half2*)wrech)[2 * j + 1] = __floats2half2_rn(v.z, v.w);
    } else if (i < P_O5) {
        int j = i - P_O4;
        int i4 = j * 4;
        int row = i4 >> 10, col = i4 & 1023;
        const float4 vx = *(const float4*)(wg + (size_t)row * 2048 + col);
        const float4 vh = *(const float4*)(wg + (size_t)row * 2048 + 1024 + col);
        ((__half2*)wgxh)[2 * j]     = __floats2half2_rn(vx.x, vx.y);
        ((__half2*)wgxh)[2 * j + 1] = __floats2half2_rn(vx.z, vx.w);
        ((__half2*)wghh)[2 * j]     = __floats2half2_rn(vh.x, vh.y);
        ((__half2*)wghh)[2 * j + 1] = __floats2half2_rn(vh.z, vh.w);
    } else if (i < P_TOTAL) {
        int j = i - P_O5;
        float4 v = ((const float4*)log_tau)[j];
        float4 o;
        o.x = (1.0f / 6.0f) * expf(-v.x);
        o.y = (1.0f / 6.0f) * expf(-v.y);
        o.z = (1.0f / 6.0f) * expf(-v.z);
        o.w = (1.0f / 6.0f) * expf(-v.w);
        ((float4*)scale)[j] = o;
    }
}

// ---------------- dual fp16 tensor-core GEMM with fully fused step ----------
// MODE 0: Oh0 = half(acc0 + b0[n]);  Oh1 = half(acc1 + b1[n])
// MODE 1: drive=tanh(eh0+acc0); gate=sigmoid(eh1+acc1);
//         o = hxh + sc[n]*(gate*drive - hxh);  Oh0 = half(o)   (fp16 state carry)
// MODE 2: same as 1 but Of = o and Of2 = o (fp32 duplicated outputs)
template <int MODE>
__global__ void __launch_bounds__(NTHREADS, 2)
ltc_fused(const __half* __restrict__ A, const __half* __restrict__ W0,
          const __half* __restrict__ W1,
          const __half* __restrict__ eh0, const __half* __restrict__ eh1,
          const float* __restrict__ b0p, const float* __restrict__ b1p,
          const __half* __restrict__ hxh, const float* __restrict__ sc,
          float* __restrict__ Of, float* __restrict__ Of2,
          __half* __restrict__ Oh0, __half* __restrict__ Oh1) {
    extern __shared__ char dsm[];
    const uint32_t sbase = (uint32_t)__cvta_generic_to_shared(dsm);
    const int tid = threadIdx.x;
    const int wid = tid >> 5, lid = tid & 31;
    const int wm = wid >> 1, wn = wid & 1;      // 4x2 warp grid; warp tile 32x32
    const int mBase = blockIdx.y * BM;
    const int nBase = blockIdx.x * BN;

    auto load_chunk = [&](int c) {
        const uint32_t st = sbase + (c % STAGES) * STAGE_BYTES;
        const __half* ga  = A  + (size_t)mBase * KDIM + c * KT;
        const __half* gb0 = W0 + (size_t)nBase * KDIM + c * KT;
        const __half* gb1 = W1 + (size_t)nBase * KDIM + c * KT;
#pragma unroll
        for (int i = 0; i < 4; i++) {
            int t = tid + i * NTHREADS;
            int row = t >> 3, cg = t & 7;
            uint32_t sw = swz128((uint32_t)(row * 128 + cg * 16));
            cp16(st + sw, ga + (size_t)row * KDIM + cg * 8);
        }
#pragma unroll
        for (int i = 0; i < 2; i++) {
            int t = tid + i * NTHREADS;
            int row = t >> 3, cg = t & 7;
            uint32_t sw = swz128((uint32_t)(row * 128 + cg * 16));
            size_t go = (size_t)row * KDIM + cg * 8;
            cp16(st + TILE_A_BYTES + sw, gb0 + go);
            cp16(st + TILE_A_BYTES + TILE_B_BYTES + sw, gb1 + go);
        }
        asm volatile("cp.async.commit_group;" ::: "memory");
    };

    float acc0[2][4][4], acc1[2][4][4];
#pragma unroll
    for (int mt = 0; mt < 2; mt++)
#pragma unroll
        for (int nt = 0; nt < 4; nt++)
#pragma unroll
            for (int e = 0; e < 4; e++) { acc0[mt][nt][e] = 0.0f; acc1[mt][nt][e] = 0.0f; }

    load_chunk(0);
    load_chunk(1);

    const int sub = lid >> 3, li = lid & 7;

    for (int kt = 0; kt < NCH; kt++) {
        asm volatile("cp.async.wait_group 1;" ::: "memory");
        __syncthreads();
        if (kt + 2 < NCH) {
            load_chunk(kt + 2);
        } else if (kt == NCH - 1 && MODE != 0) {
            // last chunk: prefetch epilogue operands (all fp16) into stages 1+2
#pragma unroll
            for (int i = 0; i < 4; i++) {
                int t = tid + i * NTHREADS;        // 0..1023: 128 rows x 8 x 16B
                int row = t >> 3, cg = t & 7;
                size_t go = (size_t)(mBase + row) * NDIM + nBase + cg * 8;
                uint32_t so = (uint32_t)(row * 128 + cg * 16);
                cp16(sbase + EPI_EH0 + so, eh0 + go);
                cp16(sbase + EPI_EH1 + so, eh1 + go);
                cp16(sbase + EPI_HXH + so, hxh + go);
            }
            asm volatile("cp.async.commit_group;" ::: "memory");
        } else {
            asm volatile("cp.async.commit_group;" ::: "memory");
        }

        const uint32_t tb = sbase + (kt % STAGES) * STAGE_BYTES;
#pragma unroll
        for (int ks = 0; ks < 4; ks++) {
            const int k0 = ks * 16;
            uint32_t af[2][4];
#pragma unroll
            for (int mt = 0; mt < 2; mt++) {
                int row = wm * 32 + mt * 16 + ((sub & 1) << 3) + li;
                int kb = (k0 + ((sub >> 1) << 3)) * 2;
                ldsm4(af[mt], tb + swz128((uint32_t)(row * 128 + kb)));
            }
            {
                uint32_t bf[2][4];
#pragma unroll
                for (int np = 0; np < 2; np++) {
                    int row = wn * 32 + np * 16 + ((sub >> 1) << 3) + li;
                    int kb = (k0 + ((sub & 1) << 3)) * 2;
                    ldsm4(bf[np], tb + TILE_A_BYTES + swz128((uint32_t)(row * 128 + kb)));
                }
#pragma unroll
                for (int mt = 0; mt < 2; mt++)
#pragma unroll
                    for (int nt = 0; nt < 4; nt++)
                        mma16816(acc0[mt][nt], af[mt], &bf[nt >> 1][(nt & 1) * 2]);
            }
            {
                uint32_t bf[2][4];
#pragma unroll
                for (int np = 0; np < 2; np++) {
                    int row = wn * 32 + np * 16 + ((sub >> 1) << 3) + li;
                    int kb = (k0 + ((sub & 1) << 3)) * 2;
                    ldsm4(bf[np], tb + TILE_A_BYTES + TILE_B_BYTES + swz128((uint32_t)(row * 128 + kb)));
                }
#pragma unroll
                for (int mt = 0; mt < 2; mt++)
#pragma unroll
                    for (int nt = 0; nt < 4; nt++)
                        mma16816(acc1[mt][nt], af[mt], &bf[nt >> 1][(nt & 1) * 2]);
            }
        }
    }
    asm volatile("cp.async.wait_group 0;" ::: "memory");
    if (MODE != 0) __syncthreads();   // epilogue tiles loaded by all threads

    // ---------------- fused epilogue ----------------
    const int l4 = lid >> 2, l2 = (lid & 3) * 2;
#pragma unroll
    for (int mt = 0; mt < 2; mt++) {
#pragma unroll
        for (int nt = 0; nt < 4; nt++) {
            const int rl0 = wm * 32 + mt * 16 + l4;   // local row in tile
            const int cl  = wn * 32 + nt * 8 + l2;    // local col in tile
            const int gc = nBase + cl;
            const float* a0 = acc0[mt][nt];
            const float* a1 = acc1[mt][nt];
            float2 scv = make_float2(0.f, 0.f), bb0 = scv, bb1 = scv;
            if (MODE == 0) {
                bb0 = *(const float2*)(b0p + gc);
                bb1 = *(const float2*)(b1p + gc);
            } else {
                scv = *(const float2*)(sc + gc);
            }
#pragma unroll
            for (int hf = 0; hf < 2; hf++) {
                const int rl = rl0 + hf * 8;
                const size_t idx = (size_t)(mBase + rl) * NDIM + gc;
                float v0x = a0[hf * 2], v0y = a0[hf * 2 + 1];
                float v1x = a1[hf * 2], v1y = a1[hf * 2 + 1];
                if (MODE == 0) {
                    *(__half2*)(Oh0 + idx) = __floats2half2_rn(v0x + bb0.x, v0y + bb0.y);
                    *(__half2*)(Oh1 + idx) = __floats2half2_rn(v1x + bb1.x, v1y + bb1.y);
                } else {
                    const uint32_t so = (uint32_t)(rl * 128 + cl * 2);
                    float2 pe0 = __half22float2(*(const __half2*)(dsm + EPI_EH0 + so));
                    float2 pe1 = __half22float2(*(const __half2*)(dsm + EPI_EH1 + so));
                    float2 hv  = __half22float2(*(const __half2*)(dsm + EPI_HXH + so));
                    float dx = fast_tanh(pe0.x + v0x);
                    float dy = fast_tanh(pe0.y + v0y);
                    float gx = 1.0f / (1.0f + __expf(-(pe1.x + v1x)));
                    float gy = 1.0f / (1.0f + __expf(-(pe1.y + v1y)));
                    float ox = hv.x + scv.x * (gx * dx - hv.x);
                    float oy = hv.y + scv.y * (gy * dy - hv.y);
                    if (MODE == 1) {
                        *(__half2*)(Oh0 + idx) = __floats2half2_rn(ox, oy);
                    } else {  // MODE 2: exact fp32 outputs, both copies
                        *(float2*)(Of + idx)  = make_float2(ox, oy);
                        *(float2*)(Of2 + idx) = make_float2(ox, oy);
                    }
                }
            }
        }
    }
}

// ---------------- launch ----------------
extern "C" void kernel_launch(void* const* d_in, const int* in_sizes, int n_in,
                              void* d_out, int out_size) {
    const float* x        = (const float*)d_in[0];
    const float* h_in     = (const float*)d_in[1];
    const float* log_tau  = (const float*)d_in[2];
    const float* W_in_w   = (const float*)d_in[3];
    const float* W_in_b   = (const float*)d_in[4];
    const float* W_rec_w  = (const float*)d_in[5];
    const float* W_gate_w = (const float*)d_in[6];
    const float* W_gate_b = (const float*)d_in[7];
    (void)in_sizes; (void)n_in;

    float *psc;
    __half *phh0, *phh1, *pidh, *pgxh, *pxh, *pwinh, *pwrech, *pwgxh, *pwghh;
    cudaGetSymbolAddress((void**)&phh0, g_hh0);
    cudaGetSymbolAddress((void**)&phh1, g_hh1);
    cudaGetSymbolAddress((void**)&pidh, g_idh);
    cudaGetSymbolAddress((void**)&pgxh, g_gxh);
    cudaGetSymbolAddress((void**)&pxh, g_xh);
    cudaGetSymbolAddress((void**)&pwinh, g_winh);
    cudaGetSymbolAddress((void**)&pwrech, g_wrech);
    cudaGetSymbolAddress((void**)&pwgxh, g_wgxh);
    cudaGetSymbolAddress((void**)&pwghh, g_wghh);
    cudaGetSymbolAddress((void**)&psc, g_scale);

    cudaFuncSetAttribute(ltc_fused<0>, cudaFuncAttributeMaxDynamicSharedMemorySize, SMEM_TOTAL);
    cudaFuncSetAttribute(ltc_fused<1>, cudaFuncAttributeMaxDynamicSharedMemorySize, SMEM_TOTAL);
    cudaFuncSetAttribute(ltc_fused<2>, cudaFuncAttributeMaxDynamicSharedMemorySize, SMEM_TOTAL);

    const size_t n = (size_t)B_SZ * NDIM;

    prep_all<<<(P_TOTAL + 255) / 256, 256>>>(
        x, h_in, W_in_w, W_rec_w, W_gate_w, log_tau,
        pxh, phh0, pwinh, pwrech, pwgxh, pwghh, psc);

    dim3 grid(NDIM / BN, B_SZ / BM);  // (16, 64) = 1024 CTAs

    ltc_fused<0><<<grid, NTHREADS, SMEM_TOTAL>>>(
        pxh, pwinh, pwgxh, nullptr, nullptr, W_in_b, W_gate_b,
        nullptr, nullptr, nullptr, nullptr, pidh, pgxh);

    float* out = (float*)d_out;
    int dup = ((size_t)out_size >= 2 * n) ? 1 : 0;
    float* out2 = dup ? (out + n) : out;

    const __half* hh_cur = phh0;   // fp16 state (GEMM A-operand AND carry)
    for (int s = 0; s < ODE_STEPS; s++) {
        __half* tgt_h = (s & 1) ? phh0 : phh1;
        if (s < ODE_STEPS - 1) {
            ltc_fused<1><<<grid, NTHREADS, SMEM_TOTAL>>>(
                hh_cur, pwrech, pwghh, pidh, pgxh, nullptr, nullptr,
                hh_cur, psc, nullptr, nullptr, tgt_h, nullptr);
            hh_cur = tgt_h;
        } else {
            ltc_fused<2><<<grid, NTHREADS, SMEM_TOTAL>>>(
                hh_cur, pwrech, pwghh, pidh, pgxh, nullptr, nullptr,
                hh_cur, psc, out, out2, nullptr, nullptr);
        }
    }
}